// round 10
// baseline (speedup 1.0000x reference)
#include <cuda_runtime.h>
#include <cuda_fp16.h>
#include <cstdint>

#define D    256
#define N0c  200000
#define N1c  40000
#define N2c  8000
#define E1c  1000000
#define E2c  200000

// ---- scratch (no allocations allowed) ----
__device__ __half g_nodesh[(size_t)N0c * D];   // fp16 node table (102 MB)
__device__ __half g_h1h[(size_t)N1c * D];      // fp16 h1
__device__ __half g_mean1h[(size_t)N1c * D];
__device__ __half g_mean2h[(size_t)N2c * D];
__device__ __half g_w1h[256 * 512];            // [Wl1 | Wr1] fp16
__device__ __half g_w2h[256 * 512];            // [Wl2 | Wr2]
__device__ float g_p[(size_t)N1c * D];         // fp32 partial (x @ Wr^T)
__device__ int g_cnt1[N1c];
__device__ int g_start1[N1c];
__device__ int g_cur1[N1c];
__device__ int g_cnt2[N2c];
__device__ int g_start2[N2c];
__device__ int g_cur2[N2c];
__device__ int g_ss1[E1c];
__device__ int g_ss2[E2c];

// ---- streams/events for captured fork/join (created pre-main, no device mem) ----
static cudaStream_t s_cvt, s_sort2;
static cudaEvent_t ev_fork, ev_hist, ev_cvt_done, ev_sort2_done;
static cudaEvent_t ev_xr1, ev_mean1, ev_xr2;
struct _StreamInit {
    _StreamInit() {
        cudaStreamCreateWithFlags(&s_cvt, cudaStreamNonBlocking);
        cudaStreamCreateWithFlags(&s_sort2, cudaStreamNonBlocking);
        cudaEventCreateWithFlags(&ev_fork, cudaEventDisableTiming);
        cudaEventCreateWithFlags(&ev_hist, cudaEventDisableTiming);
        cudaEventCreateWithFlags(&ev_cvt_done, cudaEventDisableTiming);
        cudaEventCreateWithFlags(&ev_sort2_done, cudaEventDisableTiming);
        cudaEventCreateWithFlags(&ev_xr1, cudaEventDisableTiming);
        cudaEventCreateWithFlags(&ev_mean1, cudaEventDisableTiming);
        cudaEventCreateWithFlags(&ev_xr2, cudaEventDisableTiming);
    }
};
static _StreamInit _si;

// ---------------------------------------------------------------------------
__global__ void k_init(int* __restrict__ c1, int* __restrict__ c2) {
    int i = blockIdx.x * blockDim.x + threadIdx.x;
    if (i < N1c) c1[i] = 0;
    if (i < N2c) c2[i] = 0;
}

__global__ void k_hist2(const int* __restrict__ dst1, int* __restrict__ cnt1, int e1,
                        const int* __restrict__ dst2, int* __restrict__ cnt2, int e2) {
    const int i0 = blockIdx.x * blockDim.x + threadIdx.x;
    const int stride = gridDim.x * blockDim.x;
    for (int i = i0; i < e1; i += stride) atomicAdd(&cnt1[__ldg(dst1 + i)], 1);
    for (int i = i0; i < e2; i += stride) atomicAdd(&cnt2[__ldg(dst2 + i)], 1);
}

__global__ void k_cvt(const float4* __restrict__ in, uint4* __restrict__ out, int n8) {
    int i = blockIdx.x * blockDim.x + threadIdx.x;
    int stride = gridDim.x * blockDim.x;
    for (; i < n8; i += stride) {
        float4 a = __ldg(in + 2 * i);
        float4 b = __ldg(in + 2 * i + 1);
        __half2 h[4];
        h[0] = __floats2half2_rn(a.x, a.y);
        h[1] = __floats2half2_rn(a.z, a.w);
        h[2] = __floats2half2_rn(b.x, b.y);
        h[3] = __floats2half2_rn(b.z, b.w);
        out[i] = *reinterpret_cast<uint4*>(h);
    }
}

// weights -> combined fp16 tables  w[n][k]: k<256 from Wl, k>=256 from Wr
__global__ void k_cvtw(const float* __restrict__ Wl1, const float* __restrict__ Wr1,
                       const float* __restrict__ Wl2, const float* __restrict__ Wr2,
                       uint4* __restrict__ w1h, uint4* __restrict__ w2h) {
    int i = blockIdx.x * blockDim.x + threadIdx.x;   // 0..32767
    if (i >= 32768) return;
    int layer = i >> 14;
    int li = i & 16383;
    int n = li >> 6;
    int seg = li & 63;
    const float* W = layer ? ((seg < 32) ? Wl2 : Wr2) : ((seg < 32) ? Wl1 : Wr1);
    int col = (seg & 31) * 8;
    const float4* p = reinterpret_cast<const float4*>(W + (size_t)n * 256 + col);
    float4 a = __ldg(p), b = __ldg(p + 1);
    __half2 h[4];
    h[0] = __floats2half2_rn(a.x, a.y);
    h[1] = __floats2half2_rn(a.z, a.w);
    h[2] = __floats2half2_rn(b.x, b.y);
    h[3] = __floats2half2_rn(b.z, b.w);
    (layer ? w2h : w1h)[li] = *reinterpret_cast<uint4*>(h);
}

__global__ __launch_bounds__(1024) void k_scan_t(
    const int4* __restrict__ cnt4, int4* __restrict__ start4,
    int4* __restrict__ cursor4, int n4)
{
    __shared__ int wsum[32];
    __shared__ int carry;
    const int tid = threadIdx.x;
    const int lane = tid & 31;
    const int wid = tid >> 5;
    if (tid == 0) carry = 0;
    __syncthreads();
    for (int base = 0; base < n4; base += 1024) {
        const int i = base + tid;
        int4 v = (i < n4) ? __ldg(cnt4 + i) : make_int4(0, 0, 0, 0);
        const int s = v.x + v.y + v.z + v.w;
        int x = s;
#pragma unroll
        for (int o = 1; o < 32; o <<= 1) {
            int y = __shfl_up_sync(~0u, x, o);
            if (lane >= o) x += y;
        }
        if (lane == 31) wsum[wid] = x;
        __syncthreads();
        if (tid < 32) {
            int w = wsum[tid];
#pragma unroll
            for (int o = 1; o < 32; o <<= 1) {
                int y = __shfl_up_sync(~0u, w, o);
                if (tid >= o) w += y;
            }
            wsum[tid] = w;
        }
        __syncthreads();
        const int wpref = (wid > 0) ? wsum[wid - 1] : 0;
        const int e = x - s + wpref + carry;
        if (i < n4) {
            int4 st;
            st.x = e; st.y = e + v.x; st.z = st.y + v.y; st.w = st.z + v.z;
            start4[i] = st;
            cursor4[i] = st;
        }
        __syncthreads();
        if (tid == 0) carry += wsum[31];
        __syncthreads();
    }
}

__global__ void k_sidx(const int* __restrict__ src, const int* __restrict__ dst,
                       int* __restrict__ cursor, int* __restrict__ ss, int ne) {
    int i = blockIdx.x * blockDim.x + threadIdx.x;
    if (i < ne) {
        int d = __ldg(dst + i);
        int p = atomicAdd(&cursor[d], 1);
        ss[p] = __ldg(src + i);
    }
}

__global__ __launch_bounds__(256) void k_gather_h(
    const __half* __restrict__ x, const int* __restrict__ ss,
    const int* __restrict__ start, const int* __restrict__ cnt,
    __half* __restrict__ mean, int n)
{
    int w = (blockIdx.x * blockDim.x + threadIdx.x) >> 5;
    if (w >= n) return;
    const int lane = threadIdx.x & 31;
    const int beg = __ldg(start + w);
    const int c = __ldg(cnt + w);
    const int end = beg + c;

    float acc[8];
#pragma unroll
    for (int j = 0; j < 8; j++) acc[j] = 0.f;

    int i = beg;
    for (; i + 8 <= end; i += 8) {
        int s[8];
#pragma unroll
        for (int j = 0; j < 8; j++) s[j] = __ldg(ss + i + j);
        uint4 v[8];
#pragma unroll
        for (int j = 0; j < 8; j++)
            v[j] = __ldg(reinterpret_cast<const uint4*>(x + (size_t)s[j] * D) + lane);
#pragma unroll
        for (int j = 0; j < 8; j++) {
            const __half2* p = reinterpret_cast<const __half2*>(&v[j]);
#pragma unroll
            for (int q = 0; q < 4; q++) {
                float2 f = __half22float2(p[q]);
                acc[2 * q]     += f.x;
                acc[2 * q + 1] += f.y;
            }
        }
    }
    for (; i + 4 <= end; i += 4) {
        int s[4];
#pragma unroll
        for (int j = 0; j < 4; j++) s[j] = __ldg(ss + i + j);
        uint4 v[4];
#pragma unroll
        for (int j = 0; j < 4; j++)
            v[j] = __ldg(reinterpret_cast<const uint4*>(x + (size_t)s[j] * D) + lane);
#pragma unroll
        for (int j = 0; j < 4; j++) {
            const __half2* p = reinterpret_cast<const __half2*>(&v[j]);
#pragma unroll
            for (int q = 0; q < 4; q++) {
                float2 f = __half22float2(p[q]);
                acc[2 * q]     += f.x;
                acc[2 * q + 1] += f.y;
            }
        }
    }
    for (; i < end; i++) {
        const int s0 = __ldg(ss + i);
        uint4 v0 = __ldg(reinterpret_cast<const uint4*>(x + (size_t)s0 * D) + lane);
        const __half2* p = reinterpret_cast<const __half2*>(&v0);
#pragma unroll
        for (int q = 0; q < 4; q++) {
            float2 f = __half22float2(p[q]);
            acc[2 * q]     += f.x;
            acc[2 * q + 1] += f.y;
        }
    }

    const float inv = 1.0f / fmaxf((float)c, 1.0f);
    __half2 o[4];
#pragma unroll
    for (int q = 0; q < 4; q++)
        o[q] = __floats2half2_rn(acc[2 * q] * inv, acc[2 * q + 1] * inv);
    reinterpret_cast<uint4*>(mean + (size_t)w * D)[lane] = *reinterpret_cast<uint4*>(o);
}

// ---- fp16 mma helper (m16n8k16, fp32 accumulate) ----
__device__ __forceinline__ void mma_f16(float c[4], const uint32_t a[4], const uint32_t b[2]) {
    asm volatile(
        "mma.sync.aligned.m16n8k16.row.col.f32.f16.f16.f32 "
        "{%0,%1,%2,%3}, {%4,%5,%6,%7}, {%8,%9}, {%0,%1,%2,%3};"
        : "+f"(c[0]), "+f"(c[1]), "+f"(c[2]), "+f"(c[3])
        : "r"(a[0]), "r"(a[1]), "r"(a[2]), "r"(a[3]), "r"(b[0]), "r"(b[1]));
}

// ---- half-GEMM (K=256): out-contrib = A(M x 256 fp16) @ W^T (W rows of 512, +wofs).
// Cin == null: write raw fp32 acc to outp (partial).
// Cin != null: v = tanh(acc + Cin + bias); write fp32 outf (if set) / fp16 out_h (if set).
__global__ __launch_bounds__(256) void k_gemm_half(
    const __half* __restrict__ A, const __half* __restrict__ wcomb, int wofs,
    const float* __restrict__ Cin, const float* __restrict__ bias,
    float* __restrict__ outf, __half* __restrict__ out_h, int M)
{
    __shared__ uint32_t As[2][128][12];
    __shared__ uint32_t Bs[2][128][12];

    const int m0 = blockIdx.x * 128;
    const int n0 = blockIdx.y * 128;
    const int t  = threadIdx.x;

    const int lrow = t >> 1;
    const int half = t & 1;
    const int gm   = m0 + lrow;
    const bool mval = gm < M;
    const __half* arow = A + (size_t)gm * D;
    const __half* wrow = wcomb + (size_t)(n0 + lrow) * 512 + wofs;

    const int warp = t >> 5;
    const int lane = t & 31;
    const int gid  = lane >> 2;
    const int tig  = lane & 3;
    const int wm0  = (warp & 1) * 64;
    const int wn0  = (warp >> 1) * 32;

    float acc[4][4][4];
#pragma unroll
    for (int mf = 0; mf < 4; mf++)
#pragma unroll
        for (int nf = 0; nf < 4; nf++)
#pragma unroll
            for (int r = 0; r < 4; r++) acc[mf][nf][r] = 0.f;

    auto loadA = [&](int kt) -> uint4 {
        uint4 av = make_uint4(0, 0, 0, 0);
        if (mval)
            av = *reinterpret_cast<const uint4*>(arow + kt * 16 + half * 8);
        return av;
    };
    auto loadB = [&](int kt) -> uint4 {
        return *reinterpret_cast<const uint4*>(wrow + kt * 16 + half * 8);
    };

    {
        uint4 av = loadA(0);
        uint4 bv = loadB(0);
        *reinterpret_cast<uint4*>(&As[0][lrow][half * 4]) = av;
        *reinterpret_cast<uint4*>(&Bs[0][lrow][half * 4]) = bv;
    }
    __syncthreads();

    for (int kt = 0; kt < 16; kt++) {
        const int cur = kt & 1;
        const int nxt = cur ^ 1;

        uint4 av, bv;
        if (kt < 15) {
            av = loadA(kt + 1);
            bv = loadB(kt + 1);
        }

        uint32_t af[4][4], bf[4][2];
#pragma unroll
        for (int mf = 0; mf < 4; mf++) {
            const int r = wm0 + mf * 16 + gid;
            af[mf][0] = As[cur][r][tig];
            af[mf][1] = As[cur][r + 8][tig];
            af[mf][2] = As[cur][r][tig + 4];
            af[mf][3] = As[cur][r + 8][tig + 4];
        }
#pragma unroll
        for (int nf = 0; nf < 4; nf++) {
            const int c = wn0 + nf * 8 + gid;
            bf[nf][0] = Bs[cur][c][tig];
            bf[nf][1] = Bs[cur][c][tig + 4];
        }
#pragma unroll
        for (int mf = 0; mf < 4; mf++)
#pragma unroll
            for (int nf = 0; nf < 4; nf++)
                mma_f16(acc[mf][nf], af[mf], bf[nf]);

        if (kt < 15) {
            *reinterpret_cast<uint4*>(&As[nxt][lrow][half * 4]) = av;
            *reinterpret_cast<uint4*>(&Bs[nxt][lrow][half * 4]) = bv;
        }
        __syncthreads();
    }

#pragma unroll
    for (int nf = 0; nf < 4; nf++) {
        const int cb = n0 + wn0 + nf * 8 + tig * 2;
        float bx = 0.f, by = 0.f;
        if (Cin) { bx = __ldg(bias + cb); by = __ldg(bias + cb + 1); }
#pragma unroll
        for (int mf = 0; mf < 4; mf++) {
#pragma unroll
            for (int rr = 0; rr < 2; rr++) {
                const int r = m0 + wm0 + mf * 16 + gid + rr * 8;
                if (r < M) {
                    float ax = acc[mf][nf][2 * rr];
                    float ay = acc[mf][nf][2 * rr + 1];
                    if (Cin) {
                        float2 ci = *reinterpret_cast<const float2*>(Cin + (size_t)r * D + cb);
                        float vx = tanhf(ax + ci.x + bx);
                        float vy = tanhf(ay + ci.y + by);
                        if (outf)
                            *reinterpret_cast<float2*>(outf + (size_t)r * D + cb) =
                                make_float2(vx, vy);
                        if (out_h)
                            *reinterpret_cast<__half2*>(out_h + (size_t)r * D + cb) =
                                __floats2half2_rn(vx, vy);
                    } else {
                        *reinterpret_cast<float2*>(outf + (size_t)r * D + cb) =
                            make_float2(ax, ay);
                    }
                }
            }
        }
    }
}

// ---------------------------------------------------------------------------
extern "C" void kernel_launch(void* const* d_in, const int* in_sizes, int n_in,
                              void* d_out, int out_size) {
    const float* nodes = (const float*)d_in[0];
    const float* W_l1  = (const float*)d_in[1];
    const float* b1    = (const float*)d_in[2];
    const float* W_r1  = (const float*)d_in[3];
    const float* W_l2  = (const float*)d_in[4];
    const float* b2    = (const float*)d_in[5];
    const float* W_r2  = (const float*)d_in[6];
    const int*   src1  = (const int*)d_in[7];
    const int*   dst1  = (const int*)d_in[8];
    const int*   src2  = (const int*)d_in[9];
    const int*   dst2  = (const int*)d_in[10];
    float* out = (float*)d_out;

    __half *nodesh, *h1h, *mean1h, *mean2h, *w1h, *w2h;
    float* p;
    int *cnt1, *start1, *cur1, *cnt2, *start2, *cur2, *ss1, *ss2;
    cudaGetSymbolAddress((void**)&nodesh, g_nodesh);
    cudaGetSymbolAddress((void**)&h1h,    g_h1h);
    cudaGetSymbolAddress((void**)&mean1h, g_mean1h);
    cudaGetSymbolAddress((void**)&mean2h, g_mean2h);
    cudaGetSymbolAddress((void**)&w1h,    g_w1h);
    cudaGetSymbolAddress((void**)&w2h,    g_w2h);
    cudaGetSymbolAddress((void**)&p,      g_p);
    cudaGetSymbolAddress((void**)&cnt1,   g_cnt1);
    cudaGetSymbolAddress((void**)&start1, g_start1);
    cudaGetSymbolAddress((void**)&cur1,   g_cur1);
    cudaGetSymbolAddress((void**)&cnt2,   g_cnt2);
    cudaGetSymbolAddress((void**)&start2, g_start2);
    cudaGetSymbolAddress((void**)&cur2,   g_cur2);
    cudaGetSymbolAddress((void**)&ss1,    g_ss1);
    cudaGetSymbolAddress((void**)&ss2,    g_ss2);

    // ---- default stream: init counters ----
    k_init<<<(N1c + 255) / 256, 256>>>(cnt1, cnt2);
    cudaEventRecord(ev_fork, 0);

    // ---- stream B (forked): fp16 tables, then x@Wr^T partial (overlaps gather1) ----
    cudaStreamWaitEvent(s_cvt, ev_fork, 0);
    {
        int n8 = (int)(((size_t)N0c * D) / 8);
        k_cvt<<<2368, 256, 0, s_cvt>>>((const float4*)nodes, (uint4*)nodesh, n8);
    }
    k_cvtw<<<128, 256, 0, s_cvt>>>(W_l1, W_r1, W_l2, W_r2, (uint4*)w1h, (uint4*)w2h);
    cudaEventRecord(ev_cvt_done, s_cvt);
    {   // P = nodes[:N1] @ Wr1^T   (raw fp32 partial)
        dim3 grid((N1c + 127) / 128, 2);
        k_gemm_half<<<grid, 256, 0, s_cvt>>>(nodesh, w1h, 256, ((float*)0), ((float*)0),
                                             p, ((__half*)0), N1c);
    }
    cudaEventRecord(ev_xr1, s_cvt);

    // ---- default stream: histograms then layer-1 sort ----
    k_hist2<<<1184, 256>>>(dst1, cnt1, E1c, dst2, cnt2, E2c);
    cudaEventRecord(ev_hist, 0);

    // ---- stream C (forked after hist): layer-2 sort ----
    cudaStreamWaitEvent(s_sort2, ev_hist, 0);
    k_scan_t<<<1, 1024, 0, s_sort2>>>((const int4*)cnt2, (int4*)start2, (int4*)cur2, N2c / 4);
    k_sidx<<<(E2c + 255) / 256, 256, 0, s_sort2>>>(src2, dst2, cur2, ss2, E2c);
    cudaEventRecord(ev_sort2_done, s_sort2);

    // ---- default stream: layer-1 sort, then gather1 (needs cvt) ----
    k_scan_t<<<1, 1024>>>((const int4*)cnt1, (int4*)start1, (int4*)cur1, N1c / 4);
    k_sidx<<<(E1c + 255) / 256, 256>>>(src1, dst1, cur1, ss1, E1c);
    cudaStreamWaitEvent(0, ev_cvt_done, 0);
    k_gather_h<<<(N1c * 32 + 255) / 256, 256>>>(nodesh, ss1, start1, cnt1, mean1h, N1c);

    // layer-1 mean GEMM: h1 = tanh(mean1 @ Wl1^T + P + b1) -> fp16 h1h
    cudaStreamWaitEvent(0, ev_xr1, 0);
    {
        dim3 grid((N1c + 127) / 128, 2);
        k_gemm_half<<<grid, 256>>>(mean1h, w1h, 0, p, b1, ((float*)0), h1h, N1c);
    }
    cudaEventRecord(ev_mean1, 0);

    // ---- stream B: layer-2 x-partial (overlaps gather2) ----
    cudaStreamWaitEvent(s_cvt, ev_mean1, 0);
    {   // P = h1[:N2] @ Wr2^T
        dim3 grid((N2c + 127) / 128, 2);
        k_gemm_half<<<grid, 256, 0, s_cvt>>>(h1h, w2h, 256, ((float*)0), ((float*)0),
                                             p, ((__half*)0), N2c);
    }
    cudaEventRecord(ev_xr2, s_cvt);

    // ---- default stream: gather2 then final GEMM ----
    cudaStreamWaitEvent(0, ev_sort2_done, 0);
    k_gather_h<<<(N2c * 32 + 255) / 256, 256>>>(h1h, ss2, start2, cnt2, mean2h, N2c);
    cudaStreamWaitEvent(0, ev_xr2, 0);
    {
        dim3 grid((N2c + 127) / 128, 2);
        k_gemm_half<<<grid, 256>>>(mean2h, w2h, 0, p, b2, out, ((__half*)0), N2c);
    }
}

// round 11
// speedup vs baseline: 1.1031x; 1.1031x over previous
#include <cuda_runtime.h>
#include <cuda_fp16.h>
#include <cstdint>

#define D    256
#define N0c  200000
#define N1c  40000
#define N2c  8000
#define E1c  1000000
#define E2c  200000

// ---- scratch (no allocations allowed) ----
__device__ __half g_nodesh[(size_t)N0c * D];   // fp16 node table (102 MB)
__device__ __half g_h1h[(size_t)N1c * D];      // fp16 h1
__device__ __half g_mean1h[(size_t)N1c * D];
__device__ __half g_mean2h[(size_t)N2c * D];
__device__ __half g_w1h[256 * 512];            // [Wl1 | Wr1] fp16
__device__ __half g_w2h[256 * 512];            // [Wl2 | Wr2]
__device__ int g_cnt1[N1c];
__device__ int g_start1[N1c];
__device__ int g_cur1[N1c];
__device__ int g_cnt2[N2c];
__device__ int g_start2[N2c];
__device__ int g_cur2[N2c];
__device__ int g_ss1[E1c];
__device__ int g_ss2[E2c];

// ---- streams/events for captured fork/join (created pre-main, no device mem) ----
static cudaStream_t s_cvt, s_sort2;
static cudaEvent_t ev_fork, ev_hist, ev_cvt_done, ev_sort2_done;
struct _StreamInit {
    _StreamInit() {
        cudaStreamCreateWithFlags(&s_cvt, cudaStreamNonBlocking);
        cudaStreamCreateWithFlags(&s_sort2, cudaStreamNonBlocking);
        cudaEventCreateWithFlags(&ev_fork, cudaEventDisableTiming);
        cudaEventCreateWithFlags(&ev_hist, cudaEventDisableTiming);
        cudaEventCreateWithFlags(&ev_cvt_done, cudaEventDisableTiming);
        cudaEventCreateWithFlags(&ev_sort2_done, cudaEventDisableTiming);
    }
};
static _StreamInit _si;

// ---------------------------------------------------------------------------
__global__ void k_init(int* __restrict__ c1, int* __restrict__ c2) {
    int i = blockIdx.x * blockDim.x + threadIdx.x;
    if (i < N1c) c1[i] = 0;
    if (i < N2c) c2[i] = 0;
}

__global__ void k_hist2(const int* __restrict__ dst1, int* __restrict__ cnt1, int e1,
                        const int* __restrict__ dst2, int* __restrict__ cnt2, int e2) {
    const int i0 = blockIdx.x * blockDim.x + threadIdx.x;
    const int stride = gridDim.x * blockDim.x;
    for (int i = i0; i < e1; i += stride) atomicAdd(&cnt1[__ldg(dst1 + i)], 1);
    for (int i = i0; i < e2; i += stride) atomicAdd(&cnt2[__ldg(dst2 + i)], 1);
}

__global__ void k_cvt(const float4* __restrict__ in, uint4* __restrict__ out, int n8) {
    int i = blockIdx.x * blockDim.x + threadIdx.x;
    int stride = gridDim.x * blockDim.x;
    for (; i < n8; i += stride) {
        float4 a = __ldg(in + 2 * i);
        float4 b = __ldg(in + 2 * i + 1);
        __half2 h[4];
        h[0] = __floats2half2_rn(a.x, a.y);
        h[1] = __floats2half2_rn(a.z, a.w);
        h[2] = __floats2half2_rn(b.x, b.y);
        h[3] = __floats2half2_rn(b.z, b.w);
        out[i] = *reinterpret_cast<uint4*>(h);
    }
}

// weights -> combined fp16 tables  w[n][k]: k<256 from Wl, k>=256 from Wr
__global__ void k_cvtw(const float* __restrict__ Wl1, const float* __restrict__ Wr1,
                       const float* __restrict__ Wl2, const float* __restrict__ Wr2,
                       uint4* __restrict__ w1h, uint4* __restrict__ w2h) {
    int i = blockIdx.x * blockDim.x + threadIdx.x;   // 0..32767
    if (i >= 32768) return;
    int layer = i >> 14;
    int li = i & 16383;
    int n = li >> 6;
    int seg = li & 63;
    const float* W = layer ? ((seg < 32) ? Wl2 : Wr2) : ((seg < 32) ? Wl1 : Wr1);
    int col = (seg & 31) * 8;
    const float4* p = reinterpret_cast<const float4*>(W + (size_t)n * 256 + col);
    float4 a = __ldg(p), b = __ldg(p + 1);
    __half2 h[4];
    h[0] = __floats2half2_rn(a.x, a.y);
    h[1] = __floats2half2_rn(a.z, a.w);
    h[2] = __floats2half2_rn(b.x, b.y);
    h[3] = __floats2half2_rn(b.z, b.w);
    (layer ? w2h : w1h)[li] = *reinterpret_cast<uint4*>(h);
}

__global__ __launch_bounds__(1024) void k_scan_t(
    const int4* __restrict__ cnt4, int4* __restrict__ start4,
    int4* __restrict__ cursor4, int n4)
{
    __shared__ int wsum[32];
    __shared__ int carry;
    const int tid = threadIdx.x;
    const int lane = tid & 31;
    const int wid = tid >> 5;
    if (tid == 0) carry = 0;
    __syncthreads();
    for (int base = 0; base < n4; base += 1024) {
        const int i = base + tid;
        int4 v = (i < n4) ? __ldg(cnt4 + i) : make_int4(0, 0, 0, 0);
        const int s = v.x + v.y + v.z + v.w;
        int x = s;
#pragma unroll
        for (int o = 1; o < 32; o <<= 1) {
            int y = __shfl_up_sync(~0u, x, o);
            if (lane >= o) x += y;
        }
        if (lane == 31) wsum[wid] = x;
        __syncthreads();
        if (tid < 32) {
            int w = wsum[tid];
#pragma unroll
            for (int o = 1; o < 32; o <<= 1) {
                int y = __shfl_up_sync(~0u, w, o);
                if (tid >= o) w += y;
            }
            wsum[tid] = w;
        }
        __syncthreads();
        const int wpref = (wid > 0) ? wsum[wid - 1] : 0;
        const int e = x - s + wpref + carry;
        if (i < n4) {
            int4 st;
            st.x = e; st.y = e + v.x; st.z = st.y + v.y; st.w = st.z + v.z;
            start4[i] = st;
            cursor4[i] = st;
        }
        __syncthreads();
        if (tid == 0) carry += wsum[31];
        __syncthreads();
    }
}

__global__ void k_sidx(const int* __restrict__ src, const int* __restrict__ dst,
                       int* __restrict__ cursor, int* __restrict__ ss, int ne) {
    int i = blockIdx.x * blockDim.x + threadIdx.x;
    if (i < ne) {
        int d = __ldg(dst + i);
        int p = atomicAdd(&cursor[d], 1);
        ss[p] = __ldg(src + i);
    }
}

__global__ __launch_bounds__(256) void k_gather_h(
    const __half* __restrict__ x, const int* __restrict__ ss,
    const int* __restrict__ start, const int* __restrict__ cnt,
    __half* __restrict__ mean, int n)
{
    int w = (blockIdx.x * blockDim.x + threadIdx.x) >> 5;
    if (w >= n) return;
    const int lane = threadIdx.x & 31;
    const int beg = __ldg(start + w);
    const int c = __ldg(cnt + w);
    const int end = beg + c;

    float acc[8];
#pragma unroll
    for (int j = 0; j < 8; j++) acc[j] = 0.f;

    int i = beg;
    for (; i + 8 <= end; i += 8) {
        int s[8];
#pragma unroll
        for (int j = 0; j < 8; j++) s[j] = __ldg(ss + i + j);
        uint4 v[8];
#pragma unroll
        for (int j = 0; j < 8; j++)
            v[j] = __ldg(reinterpret_cast<const uint4*>(x + (size_t)s[j] * D) + lane);
#pragma unroll
        for (int j = 0; j < 8; j++) {
            const __half2* p = reinterpret_cast<const __half2*>(&v[j]);
#pragma unroll
            for (int q = 0; q < 4; q++) {
                float2 f = __half22float2(p[q]);
                acc[2 * q]     += f.x;
                acc[2 * q + 1] += f.y;
            }
        }
    }
    for (; i + 4 <= end; i += 4) {
        int s[4];
#pragma unroll
        for (int j = 0; j < 4; j++) s[j] = __ldg(ss + i + j);
        uint4 v[4];
#pragma unroll
        for (int j = 0; j < 4; j++)
            v[j] = __ldg(reinterpret_cast<const uint4*>(x + (size_t)s[j] * D) + lane);
#pragma unroll
        for (int j = 0; j < 4; j++) {
            const __half2* p = reinterpret_cast<const __half2*>(&v[j]);
#pragma unroll
            for (int q = 0; q < 4; q++) {
                float2 f = __half22float2(p[q]);
                acc[2 * q]     += f.x;
                acc[2 * q + 1] += f.y;
            }
        }
    }
    for (; i < end; i++) {
        const int s0 = __ldg(ss + i);
        uint4 v0 = __ldg(reinterpret_cast<const uint4*>(x + (size_t)s0 * D) + lane);
        const __half2* p = reinterpret_cast<const __half2*>(&v0);
#pragma unroll
        for (int q = 0; q < 4; q++) {
            float2 f = __half22float2(p[q]);
            acc[2 * q]     += f.x;
            acc[2 * q + 1] += f.y;
        }
    }

    const float inv = 1.0f / fmaxf((float)c, 1.0f);
    __half2 o[4];
#pragma unroll
    for (int q = 0; q < 4; q++)
        o[q] = __floats2half2_rn(acc[2 * q] * inv, acc[2 * q + 1] * inv);
    reinterpret_cast<uint4*>(mean + (size_t)w * D)[lane] = *reinterpret_cast<uint4*>(o);
}

// ---- fp16 mma helper (m16n8k16, fp32 accumulate) ----
__device__ __forceinline__ void mma_f16(float c[4], const uint32_t a[4], const uint32_t b[2]) {
    asm volatile(
        "mma.sync.aligned.m16n8k16.row.col.f32.f16.f16.f32 "
        "{%0,%1,%2,%3}, {%4,%5,%6,%7}, {%8,%9}, {%0,%1,%2,%3};"
        : "+f"(c[0]), "+f"(c[1]), "+f"(c[2]), "+f"(c[3])
        : "r"(a[0]), "r"(a[1]), "r"(a[2]), "r"(a[3]), "r"(b[0]), "r"(b[1]));
}

__device__ __forceinline__ void ldsm_x4(uint32_t& r0, uint32_t& r1, uint32_t& r2,
                                        uint32_t& r3, uint32_t addr) {
    asm volatile("ldmatrix.sync.aligned.m8n8.x4.shared.b16 {%0,%1,%2,%3}, [%4];"
                 : "=r"(r0), "=r"(r1), "=r"(r2), "=r"(r3) : "r"(addr));
}

// ---- fused SAGE layer GEMM (fp16 mma.sync, fp32 accum), double-buffered smem,
//      ldmatrix fragment loads.
// A = [mean | xt] (M x 512 fp16), B^T = wcomb (256 x 512 fp16), out = tanh(A B^T + bias)
__global__ __launch_bounds__(256) void k_sage_mma_h(
    const __half* __restrict__ meanh, const __half* __restrict__ xth,
    const __half* __restrict__ wcomb, const float* __restrict__ bias,
    float* __restrict__ out, __half* __restrict__ out_h, int M)
{
    __shared__ uint32_t As[2][128][12];
    __shared__ uint32_t Bs[2][128][12];

    const int m0 = blockIdx.x * 128;
    const int n0 = blockIdx.y * 128;
    const int t  = threadIdx.x;

    const int lrow = t >> 1;
    const int half = t & 1;
    const int gm   = m0 + lrow;
    const bool mval = gm < M;
    const __half* mrow = meanh + (size_t)gm * D;
    const __half* xrow = xth  + (size_t)gm * D;
    const __half* wrow = wcomb + (size_t)(n0 + lrow) * 512;

    const int warp = t >> 5;
    const int lane = t & 31;
    const int gid  = lane >> 2;
    const int tig  = lane & 3;
    const int wm0  = (warp & 1) * 64;
    const int wn0  = (warp >> 1) * 32;

    // ldmatrix per-thread byte offsets (within one buffer)
    // A, fragment block mf: row = wm0 + mf*16 + (lane&15), u32col = (lane>>4)*4
    uint32_t a_sm[2][4], b_sm[2][2];
    {
        const uint32_t as0 = (uint32_t)__cvta_generic_to_shared(&As[0][0][0]);
        const uint32_t bs0 = (uint32_t)__cvta_generic_to_shared(&Bs[0][0][0]);
        const uint32_t bufstr = 128 * 12 * 4;
#pragma unroll
        for (int mf = 0; mf < 4; mf++) {
            uint32_t off = ((uint32_t)(wm0 + mf * 16 + (lane & 15)) * 12 +
                            (uint32_t)(lane >> 4) * 4) * 4;
            a_sm[0][mf] = as0 + off;
            a_sm[1][mf] = as0 + bufstr + off;
        }
        // B, fragment pair nf2 (nf = 2*nf2, 2*nf2+1):
        // row = wn0 + nf2*16 + ((lane>>4)&1)*8 + (lane&7), u32col = ((lane>>3)&1)*4
#pragma unroll
        for (int nf2 = 0; nf2 < 2; nf2++) {
            uint32_t off = ((uint32_t)(wn0 + nf2 * 16 + ((lane >> 4) & 1) * 8 + (lane & 7)) * 12 +
                            (uint32_t)((lane >> 3) & 1) * 4) * 4;
            b_sm[0][nf2] = bs0 + off;
            b_sm[1][nf2] = bs0 + bufstr + off;
        }
    }

    float acc[4][4][4];
#pragma unroll
    for (int mf = 0; mf < 4; mf++)
#pragma unroll
        for (int nf = 0; nf < 4; nf++)
#pragma unroll
            for (int r = 0; r < 4; r++) acc[mf][nf][r] = 0.f;

    auto loadA = [&](int kt) -> uint4 {
        const int k0 = kt * 16;
        const bool in_agg = (k0 < 256);
        const int kk0 = in_agg ? k0 : (k0 - 256);
        uint4 av = make_uint4(0, 0, 0, 0);
        if (mval) {
            const __half* sp = (in_agg ? mrow : xrow) + kk0 + half * 8;
            av = *reinterpret_cast<const uint4*>(sp);
        }
        return av;
    };
    auto loadB = [&](int kt) -> uint4 {
        return *reinterpret_cast<const uint4*>(wrow + kt * 16 + half * 8);
    };

    {
        uint4 av = loadA(0);
        uint4 bv = loadB(0);
        *reinterpret_cast<uint4*>(&As[0][lrow][half * 4]) = av;
        *reinterpret_cast<uint4*>(&Bs[0][lrow][half * 4]) = bv;
    }
    __syncthreads();

    for (int kt = 0; kt < 32; kt++) {
        const int cur = kt & 1;
        const int nxt = cur ^ 1;

        uint4 av, bv;
        if (kt < 31) {
            av = loadA(kt + 1);
            bv = loadB(kt + 1);
        }

        uint32_t af[4][4], bf[4][2];
#pragma unroll
        for (int mf = 0; mf < 4; mf++)
            ldsm_x4(af[mf][0], af[mf][1], af[mf][2], af[mf][3], a_sm[cur][mf]);
#pragma unroll
        for (int nf2 = 0; nf2 < 2; nf2++)
            ldsm_x4(bf[2 * nf2][0], bf[2 * nf2][1], bf[2 * nf2 + 1][0], bf[2 * nf2 + 1][1],
                    b_sm[cur][nf2]);

#pragma unroll
        for (int mf = 0; mf < 4; mf++)
#pragma unroll
            for (int nf = 0; nf < 4; nf++)
                mma_f16(acc[mf][nf], af[mf], bf[nf]);

        if (kt < 31) {
            *reinterpret_cast<uint4*>(&As[nxt][lrow][half * 4]) = av;
            *reinterpret_cast<uint4*>(&Bs[nxt][lrow][half * 4]) = bv;
        }
        __syncthreads();
    }

#pragma unroll
    for (int nf = 0; nf < 4; nf++) {
        const int cb = n0 + wn0 + nf * 8 + tig * 2;
        const float bx = __ldg(bias + cb);
        const float by = __ldg(bias + cb + 1);
#pragma unroll
        for (int mf = 0; mf < 4; mf++) {
            const int r0 = m0 + wm0 + mf * 16 + gid;
            if (r0 < M) {
                float vx = tanhf(acc[mf][nf][0] + bx);
                float vy = tanhf(acc[mf][nf][1] + by);
                if (out)
                    *reinterpret_cast<float2*>(out + (size_t)r0 * D + cb) = make_float2(vx, vy);
                if (out_h)
                    *reinterpret_cast<__half2*>(out_h + (size_t)r0 * D + cb) =
                        __floats2half2_rn(vx, vy);
            }
            const int r1 = r0 + 8;
            if (r1 < M) {
                float vx = tanhf(acc[mf][nf][2] + bx);
                float vy = tanhf(acc[mf][nf][3] + by);
                if (out)
                    *reinterpret_cast<float2*>(out + (size_t)r1 * D + cb) = make_float2(vx, vy);
                if (out_h)
                    *reinterpret_cast<__half2*>(out_h + (size_t)r1 * D + cb) =
                        __floats2half2_rn(vx, vy);
            }
        }
    }
}

// ---------------------------------------------------------------------------
extern "C" void kernel_launch(void* const* d_in, const int* in_sizes, int n_in,
                              void* d_out, int out_size) {
    const float* nodes = (const float*)d_in[0];
    const float* W_l1  = (const float*)d_in[1];
    const float* b1    = (const float*)d_in[2];
    const float* W_r1  = (const float*)d_in[3];
    const float* W_l2  = (const float*)d_in[4];
    const float* b2    = (const float*)d_in[5];
    const float* W_r2  = (const float*)d_in[6];
    const int*   src1  = (const int*)d_in[7];
    const int*   dst1  = (const int*)d_in[8];
    const int*   src2  = (const int*)d_in[9];
    const int*   dst2  = (const int*)d_in[10];
    float* out = (float*)d_out;

    __half *nodesh, *h1h, *mean1h, *mean2h, *w1h, *w2h;
    int *cnt1, *start1, *cur1, *cnt2, *start2, *cur2, *ss1, *ss2;
    cudaGetSymbolAddress((void**)&nodesh, g_nodesh);
    cudaGetSymbolAddress((void**)&h1h,    g_h1h);
    cudaGetSymbolAddress((void**)&mean1h, g_mean1h);
    cudaGetSymbolAddress((void**)&mean2h, g_mean2h);
    cudaGetSymbolAddress((void**)&w1h,    g_w1h);
    cudaGetSymbolAddress((void**)&w2h,    g_w2h);
    cudaGetSymbolAddress((void**)&cnt1,   g_cnt1);
    cudaGetSymbolAddress((void**)&start1, g_start1);
    cudaGetSymbolAddress((void**)&cur1,   g_cur1);
    cudaGetSymbolAddress((void**)&cnt2,   g_cnt2);
    cudaGetSymbolAddress((void**)&start2, g_start2);
    cudaGetSymbolAddress((void**)&cur2,   g_cur2);
    cudaGetSymbolAddress((void**)&ss1,    g_ss1);
    cudaGetSymbolAddress((void**)&ss2,    g_ss2);

    // ---- default stream: init counters ----
    k_init<<<(N1c + 255) / 256, 256>>>(cnt1, cnt2);
    cudaEventRecord(ev_fork, 0);

    // ---- stream B (forked): fp16 table + weight conversion ----
    cudaStreamWaitEvent(s_cvt, ev_fork, 0);
    {
        int n8 = (int)(((size_t)N0c * D) / 8);
        k_cvt<<<2368, 256, 0, s_cvt>>>((const float4*)nodes, (uint4*)nodesh, n8);
    }
    k_cvtw<<<128, 256, 0, s_cvt>>>(W_l1, W_r1, W_l2, W_r2, (uint4*)w1h, (uint4*)w2h);
    cudaEventRecord(ev_cvt_done, s_cvt);

    // ---- default stream: histograms then layer-1 sort ----
    k_hist2<<<1184, 256>>>(dst1, cnt1, E1c, dst2, cnt2, E2c);
    cudaEventRecord(ev_hist, 0);

    // ---- stream C (forked after hist): layer-2 sort ----
    cudaStreamWaitEvent(s_sort2, ev_hist, 0);
    k_scan_t<<<1, 1024, 0, s_sort2>>>((const int4*)cnt2, (int4*)start2, (int4*)cur2, N2c / 4);
    k_sidx<<<(E2c + 255) / 256, 256, 0, s_sort2>>>(src2, dst2, cur2, ss2, E2c);
    cudaEventRecord(ev_sort2_done, s_sort2);

    // ---- default stream: layer-1 sort ----
    k_scan_t<<<1, 1024>>>((const int4*)cnt1, (int4*)start1, (int4*)cur1, N1c / 4);
    k_sidx<<<(E1c + 255) / 256, 256>>>(src1, dst1, cur1, ss1, E1c);

    // join conversions, then layer-1 compute
    cudaStreamWaitEvent(0, ev_cvt_done, 0);
    k_gather_h<<<(N1c * 32 + 255) / 256, 256>>>(nodesh, ss1, start1, cnt1, mean1h, N1c);
    {
        dim3 grid((N1c + 127) / 128, 2);
        k_sage_mma_h<<<grid, 256>>>(mean1h, nodesh, w1h, b1, ((float*)0), h1h, N1c);
    }

    // join layer-2 sort, then layer-2 compute
    cudaStreamWaitEvent(0, ev_sort2_done, 0);
    k_gather_h<<<(N2c * 32 + 255) / 256, 256>>>(h1h, ss2, start2, cnt2, mean2h, N2c);
    {
        dim3 grid((N2c + 127) / 128, 2);
        k_sage_mma_h<<<grid, 256>>>(mean2h, h1h, w2h, b2, out, ((__half*)0), N2c);
    }
}